// round 1
// baseline (speedup 1.0000x reference)
#include <cuda_runtime.h>
#include <cuda_bf16.h>
#include <math.h>

#define NN 100000
#define F_IN 500
#define HD 128
#define NC 40
#define HD2 256
#define NC2 80

__device__ float g_h1[(size_t)NN * HD];     // x @ W1
__device__ float g_R1[(size_t)NN * HD2];    // acc -> relu(concat) in place
__device__ float g_h2[(size_t)NN * NC];     // R1 @ W2
__device__ float g_R2[(size_t)NN * NC2];    // layer-2 acc
__device__ float g_dinv_s[NN];              // deg -> dinv in place
__device__ float g_dinv_k[NN];
__device__ int   g_is64;

// ---------------- dtype detection (int32 vs int64 edge indices) -------------
__global__ void detect_kernel(const void* edges) {
    __shared__ int bad;
    if (threadIdx.x == 0) bad = 0;
    __syncthreads();
    const long long* p = (const long long*)edges;
    for (int i = threadIdx.x; i < 2048; i += blockDim.x) {
        long long v = p[i];
        if (v < 0 || v >= NN) bad = 1;
    }
    __syncthreads();
    if (threadIdx.x == 0) g_is64 = bad ? 0 : 1;
}

__device__ __forceinline__ int edge_at(const void* edges, long long idx, bool is64) {
    return is64 ? (int)((const long long*)edges)[idx] : ((const int*)edges)[idx];
}

// ---------------- init accumulators + degrees -------------------------------
__global__ void init_kernel() {
    int i = blockIdx.x * blockDim.x + threadIdx.x;
    float4 z = make_float4(0.f, 0.f, 0.f, 0.f);
    float4 one = make_float4(1.f, 1.f, 1.f, 1.f);
    if (i < NN * (HD2 / 4)) ((float4*)g_R1)[i] = z;
    if (i < NN * (NC2 / 4)) ((float4*)g_R2)[i] = z;
    if (i < NN / 4) { ((float4*)g_dinv_s)[i] = one; ((float4*)g_dinv_k)[i] = one; }
}

__global__ void deg_kernel(const void* edges, int E, float* deg) {
    int e = blockIdx.x * blockDim.x + threadIdx.x;
    if (e >= E) return;
    bool is64 = g_is64;
    int dst = edge_at(edges, (long long)E + e, is64);
    atomicAdd(&deg[dst], 1.0f);
}

__global__ void dinv_kernel() {
    int i = blockIdx.x * blockDim.x + threadIdx.x;
    if (i < NN) {
        g_dinv_s[i] = rsqrtf(g_dinv_s[i]);
        g_dinv_k[i] = rsqrtf(g_dinv_k[i]);
    }
}

// ---------------- GEMM1: x[N,500] @ W1[500,128] -> g_h1 ---------------------
__global__ void __launch_bounds__(256) gemm1_kernel(const float* __restrict__ x,
                                                    const float* __restrict__ W1) {
    __shared__ float As[32][128];   // transposed [k][m]
    __shared__ float Bs[32][128];   // [k][n]
    int row0 = blockIdx.x * 128;
    int tid = threadIdx.x;
    int tx = tid & 15, ty = tid >> 4;
    float acc[8][8] = {};
    int ar = tid >> 1;            // row within tile 0..127
    int ac0 = (tid & 1) * 16;     // k-col start within tile
    int br = tid >> 3;            // 0..31
    int bc0 = (tid & 7) * 16;

    for (int k0 = 0; k0 < F_IN; k0 += 32) {
        int grow = row0 + ar;
#pragma unroll
        for (int j = 0; j < 16; j += 4) {
            int c = ac0 + j;
            float4 v = make_float4(0.f, 0.f, 0.f, 0.f);
            if (grow < NN && (k0 + c) < F_IN)
                v = *(const float4*)(x + (size_t)grow * F_IN + k0 + c);
            As[c + 0][ar] = v.x; As[c + 1][ar] = v.y;
            As[c + 2][ar] = v.z; As[c + 3][ar] = v.w;
        }
#pragma unroll
        for (int j = 0; j < 16; j += 4) {
            float4 v = make_float4(0.f, 0.f, 0.f, 0.f);
            if ((k0 + br) < F_IN)
                v = *(const float4*)(W1 + (size_t)(k0 + br) * HD + bc0 + j);
            *(float4*)&Bs[br][bc0 + j] = v;
        }
        __syncthreads();
#pragma unroll
        for (int kk = 0; kk < 32; kk++) {
            float a[8], b[8];
            *(float4*)(a + 0) = *(float4*)&As[kk][ty * 8 + 0];
            *(float4*)(a + 4) = *(float4*)&As[kk][ty * 8 + 4];
            *(float4*)(b + 0) = *(float4*)&Bs[kk][tx * 8 + 0];
            *(float4*)(b + 4) = *(float4*)&Bs[kk][tx * 8 + 4];
#pragma unroll
            for (int i = 0; i < 8; i++)
#pragma unroll
                for (int j = 0; j < 8; j++)
                    acc[i][j] += a[i] * b[j];
        }
        __syncthreads();
    }
#pragma unroll
    for (int i = 0; i < 8; i++) {
        int r = row0 + ty * 8 + i;
        if (r < NN) {
            *(float4*)(g_h1 + (size_t)r * HD + tx * 8 + 0) = *(float4*)&acc[i][0];
            *(float4*)(g_h1 + (size_t)r * HD + tx * 8 + 4) = *(float4*)&acc[i][4];
        }
    }
}

// ---------------- scatter 128-wide: warp per edge ---------------------------
__global__ void scatter128_kernel(const void* edges, int E,
                                  const float* __restrict__ dinv, int base) {
    int lane = threadIdx.x & 31;
    int warp = (blockIdx.x * blockDim.x + threadIdx.x) >> 5;
    if (warp >= E) return;
    bool is64 = g_is64;
    int src = edge_at(edges, warp, is64);
    int dst = edge_at(edges, (long long)E + warp, is64);
    float s = __ldg(&dinv[src]);
    float4 v = *(const float4*)(g_h1 + (size_t)src * HD + lane * 4);
    v.x *= s; v.y *= s; v.z *= s; v.w *= s;
    float* p = g_R1 + (size_t)dst * HD2 + base + lane * 4;
    asm volatile("red.global.add.v4.f32 [%0], {%1,%2,%3,%4};"
                 :: "l"(p), "f"(v.x), "f"(v.y), "f"(v.z), "f"(v.w) : "memory");
}

// ---------------- finalize layer 1: norm + self-loop + bias + relu ----------
__global__ void finalize1_kernel(const float* __restrict__ b1) {
    int i = blockIdx.x * blockDim.x + threadIdx.x;  // over N * 32 float4 groups
    if (i >= NN * (HD / 4)) return;
    int n  = i >> 5;
    int f4 = i & 31;
    float ds = g_dinv_s[n], dk = g_dinv_k[n];
    float ds2 = ds * ds, dk2 = dk * dk;
    float4 h  = *(const float4*)(g_h1 + (size_t)n * HD + f4 * 4);
    float4 bb = *(const float4*)(b1 + f4 * 4);
    float4* ps = (float4*)(g_R1 + (size_t)n * HD2 + f4 * 4);
    float4* pk = (float4*)(g_R1 + (size_t)n * HD2 + HD + f4 * 4);
    float4 as = *ps, ak = *pk;
    as.x = fmaxf(fmaf(as.x, ds, fmaf(h.x, ds2, bb.x)), 0.f);
    as.y = fmaxf(fmaf(as.y, ds, fmaf(h.y, ds2, bb.y)), 0.f);
    as.z = fmaxf(fmaf(as.z, ds, fmaf(h.z, ds2, bb.z)), 0.f);
    as.w = fmaxf(fmaf(as.w, ds, fmaf(h.w, ds2, bb.w)), 0.f);
    ak.x = fmaxf(fmaf(ak.x, dk, fmaf(h.x, dk2, bb.x)), 0.f);
    ak.y = fmaxf(fmaf(ak.y, dk, fmaf(h.y, dk2, bb.y)), 0.f);
    ak.z = fmaxf(fmaf(ak.z, dk, fmaf(h.z, dk2, bb.z)), 0.f);
    ak.w = fmaxf(fmaf(ak.w, dk, fmaf(h.w, dk2, bb.w)), 0.f);
    *ps = as; *pk = ak;
}

// ---------------- GEMM2: R1[N,256] @ W2[256,40] -> g_h2 ---------------------
__global__ void __launch_bounds__(256) gemm2_kernel(const float* __restrict__ W2) {
    __shared__ float As[64][128];  // transposed [k][m]
    __shared__ float Bs[64][NC];
    int row0 = blockIdx.x * 128;
    int tid = threadIdx.x;
    int tx = tid & 7;     // cols tx*5 .. +4
    int ty = tid >> 3;    // rows ty*4 .. +3
    float acc[4][5] = {};
    int ar = tid >> 1;          // 0..127
    int ac0 = (tid & 1) * 32;
    int br = tid >> 2;          // 0..63
    int bc0 = (tid & 3) * 10;

    for (int k0 = 0; k0 < HD2; k0 += 64) {
        int grow = row0 + ar;
#pragma unroll
        for (int j = 0; j < 32; j += 4) {
            float4 v = make_float4(0.f, 0.f, 0.f, 0.f);
            if (grow < NN)
                v = *(const float4*)(g_R1 + (size_t)grow * HD2 + k0 + ac0 + j);
            int c = ac0 + j;
            As[c + 0][ar] = v.x; As[c + 1][ar] = v.y;
            As[c + 2][ar] = v.z; As[c + 3][ar] = v.w;
        }
#pragma unroll
        for (int j = 0; j < 10; j++)
            Bs[br][bc0 + j] = W2[(size_t)(k0 + br) * NC + bc0 + j];
        __syncthreads();
#pragma unroll 16
        for (int kk = 0; kk < 64; kk++) {
            float a[4], b[5];
            *(float4*)a = *(float4*)&As[kk][ty * 4];
#pragma unroll
            for (int j = 0; j < 5; j++) b[j] = Bs[kk][tx * 5 + j];
#pragma unroll
            for (int i = 0; i < 4; i++)
#pragma unroll
                for (int j = 0; j < 5; j++)
                    acc[i][j] += a[i] * b[j];
        }
        __syncthreads();
    }
#pragma unroll
    for (int i = 0; i < 4; i++) {
        int r = row0 + ty * 4 + i;
        if (r < NN)
#pragma unroll
            for (int j = 0; j < 5; j++)
                g_h2[(size_t)r * NC + tx * 5 + j] = acc[i][j];
    }
}

// ---------------- scatter 40-wide: 10 threads per edge ----------------------
__global__ void scatter40_kernel(const void* edges, int E,
                                 const float* __restrict__ dinv, int base) {
    long long t = (long long)blockIdx.x * blockDim.x + threadIdx.x;
    if (t >= (long long)E * 10) return;
    int e = (int)(t / 10), j = (int)(t % 10);
    bool is64 = g_is64;
    int src = edge_at(edges, e, is64);
    int dst = edge_at(edges, (long long)E + e, is64);
    float s = __ldg(&dinv[src]);
    float4 v = *(const float4*)(g_h2 + (size_t)src * NC + j * 4);
    v.x *= s; v.y *= s; v.z *= s; v.w *= s;
    float* p = g_R2 + (size_t)dst * NC2 + base + j * 4;
    asm volatile("red.global.add.v4.f32 [%0], {%1,%2,%3,%4};"
                 :: "l"(p), "f"(v.x), "f"(v.y), "f"(v.z), "f"(v.w) : "memory");
}

// ---------------- final: finalize L2 + Wlin + log_softmax -------------------
__global__ void __launch_bounds__(256) final_kernel(const float* __restrict__ b2,
                                                    const float* __restrict__ Wlin,
                                                    const float* __restrict__ blin,
                                                    float* __restrict__ out) {
    __shared__ float sWT[NC2 * NC];   // transposed: sWT[j*NC + c] = Wlin[c*NC2 + j]
    __shared__ float sb2[NC], sblin[NC];
    __shared__ float sr2[8][NC2];
    int tid = threadIdx.x;
    for (int i = tid; i < NC * NC2; i += 256) {
        int c = i / NC2, j = i % NC2;
        sWT[j * NC + c] = Wlin[i];
    }
    if (tid < NC) { sb2[tid] = b2[tid]; sblin[tid] = blin[tid]; }
    __syncthreads();
    int warp = tid >> 5, lane = tid & 31;
    int node = blockIdx.x * 8 + warp;
    if (node >= NN) return;

    float ds = g_dinv_s[node], dk = g_dinv_k[node];
    float ds2 = ds * ds, dk2 = dk * dk;
    for (int j = lane; j < NC; j += 32) {
        float h = g_h2[(size_t)node * NC + j];
        sr2[warp][j]      = fmaf(g_R2[(size_t)node * NC2 + j],      ds, fmaf(h, ds2, sb2[j]));
        sr2[warp][NC + j] = fmaf(g_R2[(size_t)node * NC2 + NC + j], dk, fmaf(h, dk2, sb2[j]));
    }
    __syncwarp();

    float l1, l2 = -INFINITY;
    {
        float a = sblin[lane];
#pragma unroll 8
        for (int j = 0; j < NC2; j++) a = fmaf(sr2[warp][j], sWT[j * NC + lane], a);
        l1 = a;
    }
    if (lane < 8) {
        int c = 32 + lane;
        float a = sblin[c];
#pragma unroll 8
        for (int j = 0; j < NC2; j++) a = fmaf(sr2[warp][j], sWT[j * NC + c], a);
        l2 = a;
    }
    float m = fmaxf(l1, l2);
#pragma unroll
    for (int off = 16; off > 0; off >>= 1)
        m = fmaxf(m, __shfl_xor_sync(0xffffffffu, m, off));
    float s = expf(l1 - m) + ((lane < 8) ? expf(l2 - m) : 0.f);
#pragma unroll
    for (int off = 16; off > 0; off >>= 1)
        s += __shfl_xor_sync(0xffffffffu, s, off);
    float lse = logf(s);
    out[(size_t)node * NC + lane] = l1 - m - lse;
    if (lane < 8) out[(size_t)node * NC + 32 + lane] = l2 - m - lse;
}

// ---------------------------------------------------------------------------
extern "C" void kernel_launch(void* const* d_in, const int* in_sizes, int n_in,
                              void* d_out, int out_size) {
    const float* x    = (const float*)d_in[0];
    const void*  es   = d_in[1];
    const void*  ek   = d_in[2];
    const float* W1   = (const float*)d_in[3];
    const float* b1   = (const float*)d_in[4];
    const float* W2   = (const float*)d_in[5];
    const float* b2   = (const float*)d_in[6];
    const float* Wlin = (const float*)d_in[7];
    const float* blin = (const float*)d_in[8];
    float* out = (float*)d_out;

    int E  = in_sizes[1] / 2;
    int Ek = in_sizes[2] / 2;

    float *dinv_s, *dinv_k;
    cudaGetSymbolAddress((void**)&dinv_s, g_dinv_s);
    cudaGetSymbolAddress((void**)&dinv_k, g_dinv_k);

    detect_kernel<<<1, 256>>>(es);
    init_kernel<<<(NN * (HD2 / 4) + 255) / 256, 256>>>();
    deg_kernel<<<(E + 255) / 256, 256>>>(es, E, dinv_s);
    deg_kernel<<<(Ek + 255) / 256, 256>>>(ek, Ek, dinv_k);
    dinv_kernel<<<(NN + 255) / 256, 256>>>();

    gemm1_kernel<<<(NN + 127) / 128, 256>>>(x, W1);
    scatter128_kernel<<<(E + 7) / 8, 256>>>(es, E, dinv_s, 0);
    scatter128_kernel<<<(Ek + 7) / 8, 256>>>(ek, Ek, dinv_k, HD);
    finalize1_kernel<<<(NN * (HD / 4) + 255) / 256, 256>>>(b1);

    gemm2_kernel<<<(NN + 127) / 128, 256>>>(W2);
    {
        long long ts = (long long)E * 10;
        long long tk = (long long)Ek * 10;
        scatter40_kernel<<<(unsigned)((ts + 255) / 256), 256>>>(es, E, dinv_s, 0);
        scatter40_kernel<<<(unsigned)((tk + 255) / 256), 256>>>(ek, Ek, dinv_k, NC);
    }
    final_kernel<<<(NN + 7) / 8, 256>>>(b2, Wlin, blin, out);
}

// round 5
// speedup vs baseline: 1.1170x; 1.1170x over previous
#include <cuda_runtime.h>
#include <cuda_bf16.h>
#include <cstdint>
#include <math.h>

#define NN 100000
#define F_IN 500
#define HD 128
#define NC 40
#define HD2 256
#define NC2 80

__device__ float g_h1[(size_t)NN * HD];     // x @ W1
__device__ float g_R1[(size_t)NN * HD2];    // acc -> relu(concat) in place
__device__ float g_h2[(size_t)NN * NC];     // R1 @ W2
__device__ float g_R2[(size_t)NN * NC2];    // layer-2 acc
__device__ float g_dinv_s[NN];              // deg -> dinv in place
__device__ float g_dinv_k[NN];
__device__ int   g_is64;
// W1^T split into bf16 hi/lo, layout [chunk=8][n=128][k=64]
__device__ __nv_bfloat16 g_W1h[8 * 128 * 64];
__device__ __nv_bfloat16 g_W1l[8 * 128 * 64];

// ---------------- W1 split + transpose: [k][n] -> [chunk][n][k64] -----------
__global__ void w1split_kernel(const float* __restrict__ W1) {
    int i = blockIdx.x * blockDim.x + threadIdx.x;
    if (i >= 512 * 128) return;
    int k = i >> 7, n = i & 127;
    float v = (k < F_IN) ? W1[(size_t)k * HD + n] : 0.f;
    __nv_bfloat16 h = __float2bfloat16_rn(v);
    __nv_bfloat16 l = __float2bfloat16_rn(v - __bfloat162float(h));
    int chunk = k >> 6, kk = k & 63;
    int off = (chunk * 128 + n) * 64 + kk;
    g_W1h[off] = h;
    g_W1l[off] = l;
}

// ---------------- GEMM1 via mma.sync bf16 split: x[N,500]@W1 -> g_h1 --------
__device__ __forceinline__ void mma16816(float* c, const uint32_t* a, const uint32_t* b) {
    asm volatile("mma.sync.aligned.m16n8k16.row.col.f32.bf16.bf16.f32 "
                 "{%0,%1,%2,%3}, {%4,%5,%6,%7}, {%8,%9}, {%0,%1,%2,%3};"
                 : "+f"(c[0]), "+f"(c[1]), "+f"(c[2]), "+f"(c[3])
                 : "r"(a[0]), "r"(a[1]), "r"(a[2]), "r"(a[3]), "r"(b[0]), "r"(b[1]));
}

#define LDA 72   // padded row length (bf16) for conflict-free b32 smem loads
#define G1_SMEM (4 * 128 * LDA * 2)

__global__ void __launch_bounds__(256) gemm1_mma(const float* __restrict__ x) {
    extern __shared__ __nv_bfloat16 smem[];
    __nv_bfloat16* Ah = smem;                 // [128][LDA]
    __nv_bfloat16* Al = Ah + 128 * LDA;
    __nv_bfloat16* Bh = Al + 128 * LDA;       // [128 n][LDA]
    __nv_bfloat16* Bl = Bh + 128 * LDA;

    int tid = threadIdx.x;
    int lane = tid & 31, wid = tid >> 5;
    int wm = wid & 3, wn = wid >> 2;          // warp tile: rows wm*32, cols wn*64
    int gr = lane >> 2, tig = lane & 3;
    int row0 = blockIdx.x * 128;

    int ar = tid >> 1;                        // A-load row 0..127
    int akh = (tid & 1) * 32;                 // A-load k-half
    bool rowok = (row0 + ar) < NN;
    const float* xp = x + (size_t)(row0 + ar) * F_IN;

    float c[2][8][4];
#pragma unroll
    for (int mt = 0; mt < 2; mt++)
#pragma unroll
        for (int nt = 0; nt < 8; nt++)
#pragma unroll
            for (int q = 0; q < 4; q++) c[mt][nt][q] = 0.f;

    for (int chunk = 0; chunk < 8; chunk++) {
        int k0 = chunk * 64;
        // ---- load A: fp32 -> split bf16 hi/lo into smem ----
#pragma unroll
        for (int j = 0; j < 32; j += 8) {
            int kk = akh + j, gk = k0 + kk;
            float4 a = make_float4(0.f, 0.f, 0.f, 0.f);
            float4 b = make_float4(0.f, 0.f, 0.f, 0.f);
            if (rowok && gk < F_IN)     a = *(const float4*)(xp + gk);
            if (rowok && gk + 4 < F_IN) b = *(const float4*)(xp + gk + 4);
            float v[8] = {a.x, a.y, a.z, a.w, b.x, b.y, b.z, b.w};
            __nv_bfloat16 hb[8], lb[8];
#pragma unroll
            for (int q = 0; q < 8; q++) {
                hb[q] = __float2bfloat16_rn(v[q]);
                lb[q] = __float2bfloat16_rn(v[q] - __bfloat162float(hb[q]));
            }
            *(uint4*)&Ah[ar * LDA + kk] = *(uint4*)hb;
            *(uint4*)&Al[ar * LDA + kk] = *(uint4*)lb;
        }
        // ---- load B: copy pre-split W1^T [n][k64] ----
        {
            const uint4* sh = (const uint4*)(g_W1h + chunk * 128 * 64);
            const uint4* sl = (const uint4*)(g_W1l + chunk * 128 * 64);
#pragma unroll
            for (int it = 0; it < 4; it++) {
                int idx = tid + it * 256;           // 1024 uint4 = 128n x 8 groups
                int n = idx >> 3, kg = idx & 7;
                *(uint4*)&Bh[n * LDA + kg * 8] = sh[idx];
                *(uint4*)&Bl[n * LDA + kg * 8] = sl[idx];
            }
        }
        __syncthreads();
        // ---- 4 k-steps of 16 ----
#pragma unroll
        for (int ks = 0; ks < 4; ks++) {
            int kk = ks * 16;
            uint32_t ah[2][4], al[2][4], bhf[8][2], blf[8][2];
#pragma unroll
            for (int mt = 0; mt < 2; mt++) {
                int rb = wm * 32 + mt * 16;
                ah[mt][0] = *(uint32_t*)&Ah[(rb + gr) * LDA + kk + tig * 2];
                ah[mt][1] = *(uint32_t*)&Ah[(rb + gr + 8) * LDA + kk + tig * 2];
                ah[mt][2] = *(uint32_t*)&Ah[(rb + gr) * LDA + kk + tig * 2 + 8];
                ah[mt][3] = *(uint32_t*)&Ah[(rb + gr + 8) * LDA + kk + tig * 2 + 8];
                al[mt][0] = *(uint32_t*)&Al[(rb + gr) * LDA + kk + tig * 2];
                al[mt][1] = *(uint32_t*)&Al[(rb + gr + 8) * LDA + kk + tig * 2];
                al[mt][2] = *(uint32_t*)&Al[(rb + gr) * LDA + kk + tig * 2 + 8];
                al[mt][3] = *(uint32_t*)&Al[(rb + gr + 8) * LDA + kk + tig * 2 + 8];
            }
#pragma unroll
            for (int nt = 0; nt < 8; nt++) {
                int nb = wn * 64 + nt * 8 + gr;
                bhf[nt][0] = *(uint32_t*)&Bh[nb * LDA + kk + tig * 2];
                bhf[nt][1] = *(uint32_t*)&Bh[nb * LDA + kk + tig * 2 + 8];
                blf[nt][0] = *(uint32_t*)&Bl[nb * LDA + kk + tig * 2];
                blf[nt][1] = *(uint32_t*)&Bl[nb * LDA + kk + tig * 2 + 8];
            }
#pragma unroll
            for (int mt = 0; mt < 2; mt++)
#pragma unroll
                for (int nt = 0; nt < 8; nt++) {
                    mma16816(c[mt][nt], ah[mt], bhf[nt]);
                    mma16816(c[mt][nt], al[mt], bhf[nt]);
                    mma16816(c[mt][nt], ah[mt], blf[nt]);
                }
        }
        __syncthreads();
    }
    // ---- epilogue ----
#pragma unroll
    for (int mt = 0; mt < 2; mt++) {
        int r0 = row0 + wm * 32 + mt * 16 + gr;
#pragma unroll
        for (int nt = 0; nt < 8; nt++) {
            int cc = wn * 64 + nt * 8 + tig * 2;
            if (r0 < NN)
                *(float2*)(g_h1 + (size_t)r0 * HD + cc) = make_float2(c[mt][nt][0], c[mt][nt][1]);
            if (r0 + 8 < NN)
                *(float2*)(g_h1 + (size_t)(r0 + 8) * HD + cc) = make_float2(c[mt][nt][2], c[mt][nt][3]);
        }
    }
}

// ---------------- dtype detection (int32 vs int64 edge indices) -------------
__global__ void detect_kernel(const void* edges) {
    __shared__ int bad;
    if (threadIdx.x == 0) bad = 0;
    __syncthreads();
    const long long* p = (const long long*)edges;
    for (int i = threadIdx.x; i < 2048; i += blockDim.x) {
        long long v = p[i];
        if (v < 0 || v >= NN) bad = 1;
    }
    __syncthreads();
    if (threadIdx.x == 0) g_is64 = bad ? 0 : 1;
}

__device__ __forceinline__ int edge_at(const void* edges, long long idx, bool is64) {
    return is64 ? (int)((const long long*)edges)[idx] : ((const int*)edges)[idx];
}

// ---------------- init accumulators + degrees -------------------------------
__global__ void init_kernel() {
    int i = blockIdx.x * blockDim.x + threadIdx.x;
    float4 z = make_float4(0.f, 0.f, 0.f, 0.f);
    float4 one = make_float4(1.f, 1.f, 1.f, 1.f);
    if (i < NN * (HD2 / 4)) ((float4*)g_R1)[i] = z;
    if (i < NN * (NC2 / 4)) ((float4*)g_R2)[i] = z;
    if (i < NN / 4) { ((float4*)g_dinv_s)[i] = one; ((float4*)g_dinv_k)[i] = one; }
}

__global__ void deg_kernel(const void* edges, int E, float* deg) {
    int e = blockIdx.x * blockDim.x + threadIdx.x;
    if (e >= E) return;
    bool is64 = g_is64;
    int dst = edge_at(edges, (long long)E + e, is64);
    atomicAdd(&deg[dst], 1.0f);
}

__global__ void dinv_kernel() {
    int i = blockIdx.x * blockDim.x + threadIdx.x;
    if (i < NN) {
        g_dinv_s[i] = rsqrtf(g_dinv_s[i]);
        g_dinv_k[i] = rsqrtf(g_dinv_k[i]);
    }
}

// ---------------- scatter 128-wide: warp per edge ---------------------------
__global__ void scatter128_kernel(const void* edges, int E,
                                  const float* __restrict__ dinv, int base) {
    int lane = threadIdx.x & 31;
    int warp = (blockIdx.x * blockDim.x + threadIdx.x) >> 5;
    if (warp >= E) return;
    bool is64 = g_is64;
    int src = edge_at(edges, warp, is64);
    int dst = edge_at(edges, (long long)E + warp, is64);
    float s = __ldg(&dinv[src]);
    float4 v = *(const float4*)(g_h1 + (size_t)src * HD + lane * 4);
    v.x *= s; v.y *= s; v.z *= s; v.w *= s;
    float* p = g_R1 + (size_t)dst * HD2 + base + lane * 4;
    asm volatile("red.global.add.v4.f32 [%0], {%1,%2,%3,%4};"
                 :: "l"(p), "f"(v.x), "f"(v.y), "f"(v.z), "f"(v.w) : "memory");
}

// ---------------- finalize layer 1: norm + self-loop + bias + relu ----------
__global__ void finalize1_kernel(const float* __restrict__ b1) {
    int i = blockIdx.x * blockDim.x + threadIdx.x;
    if (i >= NN * (HD / 4)) return;
    int n  = i >> 5;
    int f4 = i & 31;
    float ds = g_dinv_s[n], dk = g_dinv_k[n];
    float ds2 = ds * ds, dk2 = dk * dk;
    float4 h  = *(const float4*)(g_h1 + (size_t)n * HD + f4 * 4);
    float4 bb = *(const float4*)(b1 + f4 * 4);
    float4* ps = (float4*)(g_R1 + (size_t)n * HD2 + f4 * 4);
    float4* pk = (float4*)(g_R1 + (size_t)n * HD2 + HD + f4 * 4);
    float4 as = *ps, ak = *pk;
    as.x = fmaxf(fmaf(as.x, ds, fmaf(h.x, ds2, bb.x)), 0.f);
    as.y = fmaxf(fmaf(as.y, ds, fmaf(h.y, ds2, bb.y)), 0.f);
    as.z = fmaxf(fmaf(as.z, ds, fmaf(h.z, ds2, bb.z)), 0.f);
    as.w = fmaxf(fmaf(as.w, ds, fmaf(h.w, ds2, bb.w)), 0.f);
    ak.x = fmaxf(fmaf(ak.x, dk, fmaf(h.x, dk2, bb.x)), 0.f);
    ak.y = fmaxf(fmaf(ak.y, dk, fmaf(h.y, dk2, bb.y)), 0.f);
    ak.z = fmaxf(fmaf(ak.z, dk, fmaf(h.z, dk2, bb.z)), 0.f);
    ak.w = fmaxf(fmaf(ak.w, dk, fmaf(h.w, dk2, bb.w)), 0.f);
    *ps = as; *pk = ak;
}

// ---------------- GEMM2: R1[N,256] @ W2[256,40] -> g_h2 ---------------------
__global__ void __launch_bounds__(256) gemm2_kernel(const float* __restrict__ W2) {
    __shared__ float As[64][128];
    __shared__ float Bs[64][NC];
    int row0 = blockIdx.x * 128;
    int tid = threadIdx.x;
    int tx = tid & 7;
    int ty = tid >> 3;
    float acc[4][5] = {};
    int ar = tid >> 1;
    int ac0 = (tid & 1) * 32;
    int br = tid >> 2;
    int bc0 = (tid & 3) * 10;

    for (int k0 = 0; k0 < HD2; k0 += 64) {
        int grow = row0 + ar;
#pragma unroll
        for (int j = 0; j < 32; j += 4) {
            float4 v = make_float4(0.f, 0.f, 0.f, 0.f);
            if (grow < NN)
                v = *(const float4*)(g_R1 + (size_t)grow * HD2 + k0 + ac0 + j);
            int cidx = ac0 + j;
            As[cidx + 0][ar] = v.x; As[cidx + 1][ar] = v.y;
            As[cidx + 2][ar] = v.z; As[cidx + 3][ar] = v.w;
        }
#pragma unroll
        for (int j = 0; j < 10; j++)
            Bs[br][bc0 + j] = W2[(size_t)(k0 + br) * NC + bc0 + j];
        __syncthreads();
#pragma unroll 16
        for (int kk = 0; kk < 64; kk++) {
            float a[4], b[5];
            *(float4*)a = *(float4*)&As[kk][ty * 4];
#pragma unroll
            for (int j = 0; j < 5; j++) b[j] = Bs[kk][tx * 5 + j];
#pragma unroll
            for (int i = 0; i < 4; i++)
#pragma unroll
                for (int j = 0; j < 5; j++)
                    acc[i][j] += a[i] * b[j];
        }
        __syncthreads();
    }
#pragma unroll
    for (int i = 0; i < 4; i++) {
        int r = row0 + ty * 4 + i;
        if (r < NN)
#pragma unroll
            for (int j = 0; j < 5; j++)
                g_h2[(size_t)r * NC + tx * 5 + j] = acc[i][j];
    }
}

// ---------------- scatter 40-wide: 10 threads per edge ----------------------
__global__ void scatter40_kernel(const void* edges, int E,
                                 const float* __restrict__ dinv, int base) {
    long long t = (long long)blockIdx.x * blockDim.x + threadIdx.x;
    if (t >= (long long)E * 10) return;
    int e = (int)(t / 10), j = (int)(t % 10);
    bool is64 = g_is64;
    int src = edge_at(edges, e, is64);
    int dst = edge_at(edges, (long long)E + e, is64);
    float s = __ldg(&dinv[src]);
    float4 v = *(const float4*)(g_h2 + (size_t)src * NC + j * 4);
    v.x *= s; v.y *= s; v.z *= s; v.w *= s;
    float* p = g_R2 + (size_t)dst * NC2 + base + j * 4;
    asm volatile("red.global.add.v4.f32 [%0], {%1,%2,%3,%4};"
                 :: "l"(p), "f"(v.x), "f"(v.y), "f"(v.z), "f"(v.w) : "memory");
}

// ---------------- final: finalize L2 + Wlin + log_softmax -------------------
__global__ void __launch_bounds__(256) final_kernel(const float* __restrict__ b2,
                                                    const float* __restrict__ Wlin,
                                                    const float* __restrict__ blin,
                                                    float* __restrict__ out) {
    __shared__ float sWT[NC2 * NC];
    __shared__ float sb2[NC], sblin[NC];
    __shared__ float sr2[8][NC2];
    int tid = threadIdx.x;
    for (int i = tid; i < NC * NC2; i += 256) {
        int cidx = i / NC2, j = i % NC2;
        sWT[j * NC + cidx] = Wlin[i];
    }
    if (tid < NC) { sb2[tid] = b2[tid]; sblin[tid] = blin[tid]; }
    __syncthreads();
    int warp = tid >> 5, lane = tid & 31;
    int node = blockIdx.x * 8 + warp;
    if (node >= NN) return;

    float ds = g_dinv_s[node], dk = g_dinv_k[node];
    float ds2 = ds * ds, dk2 = dk * dk;
    for (int j = lane; j < NC; j += 32) {
        float h = g_h2[(size_t)node * NC + j];
        sr2[warp][j]      = fmaf(g_R2[(size_t)node * NC2 + j],      ds, fmaf(h, ds2, sb2[j]));
        sr2[warp][NC + j] = fmaf(g_R2[(size_t)node * NC2 + NC + j], dk, fmaf(h, dk2, sb2[j]));
    }
    __syncwarp();

    float l1, l2 = -INFINITY;
    {
        float a = sblin[lane];
#pragma unroll 8
        for (int j = 0; j < NC2; j++) a = fmaf(sr2[warp][j], sWT[j * NC + lane], a);
        l1 = a;
    }
    if (lane < 8) {
        int cidx = 32 + lane;
        float a = sblin[cidx];
#pragma unroll 8
        for (int j = 0; j < NC2; j++) a = fmaf(sr2[warp][j], sWT[j * NC + cidx], a);
        l2 = a;
    }
    float m = fmaxf(l1, l2);
#pragma unroll
    for (int off = 16; off > 0; off >>= 1)
        m = fmaxf(m, __shfl_xor_sync(0xffffffffu, m, off));
    float s = expf(l1 - m) + ((lane < 8) ? expf(l2 - m) : 0.f);
#pragma unroll
    for (int off = 16; off > 0; off >>= 1)
        s += __shfl_xor_sync(0xffffffffu, s, off);
    float lse = logf(s);
    out[(size_t)node * NC + lane] = l1 - m - lse;
    if (lane < 8) out[(size_t)node * NC + 32 + lane] = l2 - m - lse;
}

// ---------------------------------------------------------------------------
extern "C" void kernel_launch(void* const* d_in, const int* in_sizes, int n_in,
                              void* d_out, int out_size) {
    const float* x    = (const float*)d_in[0];
    const void*  es   = d_in[1];
    const void*  ek   = d_in[2];
    const float* W1   = (const float*)d_in[3];
    const float* b1   = (const float*)d_in[4];
    const float* W2   = (const float*)d_in[5];
    const float* b2   = (const float*)d_in[6];
    const float* Wlin = (const float*)d_in[7];
    const float* blin = (const float*)d_in[8];
    float* out = (float*)d_out;

    int E  = in_sizes[1] / 2;
    int Ek = in_sizes[2] / 2;

    float *dinv_s, *dinv_k;
    cudaGetSymbolAddress((void**)&dinv_s, g_dinv_s);
    cudaGetSymbolAddress((void**)&dinv_k, g_dinv_k);

    static int smem_set = 0;
    if (!smem_set) {
        cudaFuncSetAttribute(gemm1_mma, cudaFuncAttributeMaxDynamicSharedMemorySize, G1_SMEM);
        smem_set = 1;
    }

    detect_kernel<<<1, 256>>>(es);
    init_kernel<<<(NN * (HD2 / 4) + 255) / 256, 256>>>();
    deg_kernel<<<(E + 255) / 256, 256>>>(es, E, dinv_s);
    deg_kernel<<<(Ek + 255) / 256, 256>>>(ek, Ek, dinv_k);
    dinv_kernel<<<(NN + 255) / 256, 256>>>();

    w1split_kernel<<<(512 * 128 + 255) / 256, 256>>>(W1);
    gemm1_mma<<<(NN + 127) / 128, 256, G1_SMEM>>>(x);

    scatter128_kernel<<<(E + 7) / 8, 256>>>(es, E, dinv_s, 0);
    scatter128_kernel<<<(Ek + 7) / 8, 256>>>(ek, Ek, dinv_k, HD);
    finalize1_kernel<<<(NN * (HD / 4) + 255) / 256, 256>>>(b1);

    gemm2_kernel<<<(NN + 127) / 128, 256>>>(W2);
    {
        long long ts = (long long)E * 10;
        long long tk = (long long)Ek * 10;
        scatter40_kernel<<<(unsigned)((ts + 255) / 256), 256>>>(es, E, dinv_s, 0);
        scatter40_kernel<<<(unsigned)((tk + 255) / 256), 256>>>(ek, Ek, dinv_k, NC);
    }
    final_kernel<<<(NN + 7) / 8, 256>>>(b2, Wlin, blin, out);
}